// round 1
// baseline (speedup 1.0000x reference)
#include <cuda_runtime.h>
#include <math.h>

// ---------------- problem constants ----------------
#define NB 4096   // batch

// ---------------- scratch (device globals; no allocs) ----------------
__device__ float g_tw1[32 * 25];          // ternarized conv1 weights
__device__ float g_tw2[64 * 800];         // ternarized conv2 weights [oc][800]
__device__ float g_tw2t[800 * 64];        // transposed: [k][oc]
__device__ float g_twf1[512 * 1024];      // ternarized fc1
__device__ float g_twf2[10 * 512];        // ternarized fc2

__device__ float g_conv1[(size_t)NB * 32 * 576];   // [n][32][24][24]
__device__ float g_ps1[NB * 32];
__device__ float g_pq1[NB * 32];
__device__ float g_pool1[(size_t)NB * 32 * 144];   // [n][32][12][12]
__device__ float g_conv2[(size_t)NB * 64 * 64];    // [n][64][8][8]
__device__ float g_ps2[NB * 64];
__device__ float g_pq2[NB * 64];
__device__ float g_pool2[(size_t)NB * 1024];       // [n][64][4][4] == [n][1024]
__device__ float g_fc1o[(size_t)NB * 512];

__device__ float g_bns1[32], g_bnb1[32];  // BN1 fused scale/shift
__device__ float g_bns2[64], g_bnb2[64];

// ---------------- ternarize (TWN): per-output-channel ----------------
// delta = 0.7*mean(|w|); alpha = mean(|w| where |w|>delta); out = sign*alpha where |w|>delta
__global__ void __launch_bounds__(256) k_ternarize(const float* __restrict__ w,
                                                   int which, int per_ch) {
    float* dst = (which == 0) ? g_tw1 : (which == 1) ? g_tw2
               : (which == 2) ? g_twf1 : g_twf2;
    int ch = blockIdx.x;
    const float* wc = w + (size_t)ch * per_ch;
    float* oc = dst + (size_t)ch * per_ch;
    int tid = threadIdx.x;
    __shared__ float sA[8], sB[8];
    __shared__ float s_delta, s_alpha;

    float s = 0.f;
    for (int i = tid; i < per_ch; i += 256) s += fabsf(wc[i]);
    for (int o = 16; o; o >>= 1) s += __shfl_xor_sync(0xffffffffu, s, o);
    if ((tid & 31) == 0) sA[tid >> 5] = s;
    __syncthreads();
    if (tid == 0) {
        float t = 0.f;
        for (int i = 0; i < 8; i++) t += sA[i];
        s_delta = 0.7f * t / (float)per_ch;
    }
    __syncthreads();
    float delta = s_delta;

    float sa = 0.f, cn = 0.f;
    for (int i = tid; i < per_ch; i += 256) {
        float a = fabsf(wc[i]);
        if (a > delta) { sa += a; cn += 1.f; }
    }
    for (int o = 16; o; o >>= 1) {
        sa += __shfl_xor_sync(0xffffffffu, sa, o);
        cn += __shfl_xor_sync(0xffffffffu, cn, o);
    }
    __syncthreads();
    if ((tid & 31) == 0) { sA[tid >> 5] = sa; sB[tid >> 5] = cn; }
    __syncthreads();
    if (tid == 0) {
        float a = 0.f, c = 0.f;
        for (int i = 0; i < 8; i++) { a += sA[i]; c += sB[i]; }
        s_alpha = a / c;
    }
    __syncthreads();
    float alpha = s_alpha;
    for (int i = tid; i < per_ch; i += 256) {
        float v = wc[i];
        oc[i] = (fabsf(v) > delta) ? copysignf(alpha, v) : 0.f;
    }
}

__global__ void k_transpose_w2() {
    int i = blockIdx.x * 256 + threadIdx.x;
    if (i < 64 * 800) {
        int oc = i / 800, k = i - oc * 800;
        g_tw2t[k * 64 + oc] = g_tw2[i];
    }
}

// ---------------- conv1: [n,1,28,28] -> [n,32,24,24] + per-image BN partials ----------------
__global__ void __launch_bounds__(256) k_conv1(const float* __restrict__ x,
                                               const float* __restrict__ bias) {
    __shared__ float s_x[784];
    __shared__ float s_w[800];
    __shared__ float s_b[32];
    __shared__ float s_rs[8], s_rq[8];
    __shared__ float s_sum[32], s_sq[32];
    int n = blockIdx.x, tid = threadIdx.x;
    for (int i = tid; i < 784; i += 256) s_x[i] = x[(size_t)n * 784 + i];
    for (int i = tid; i < 800; i += 256) s_w[i] = g_tw1[i];
    if (tid < 32) s_b[tid] = bias[tid];
    __syncthreads();
    int lane = tid & 31, wid = tid >> 5;

    for (int ocn = 0; ocn < 32; ocn++) {
        float wr[25];
#pragma unroll
        for (int i = 0; i < 25; i++) wr[i] = s_w[ocn * 25 + i];
        float bs = s_b[ocn];
        float ls = 0.f, lq = 0.f;
        float* outp = &g_conv1[((size_t)n * 32 + ocn) * 576];
        // 288 groups of 2 horizontally-adjacent outputs (register reuse of x)
        for (int g = tid; g < 288; g += 256) {
            int pos = g * 2;
            int oy = pos / 24, ox = pos - oy * 24;
            const float* xp = &s_x[oy * 28 + ox];
            float a0 = bs, a1 = bs;
#pragma unroll
            for (int ky = 0; ky < 5; ky++) {
                float x0 = xp[ky * 28 + 0], x1 = xp[ky * 28 + 1], x2 = xp[ky * 28 + 2];
                float x3 = xp[ky * 28 + 3], x4 = xp[ky * 28 + 4], x5 = xp[ky * 28 + 5];
                a0 += x0 * wr[ky * 5 + 0] + x1 * wr[ky * 5 + 1] + x2 * wr[ky * 5 + 2]
                    + x3 * wr[ky * 5 + 3] + x4 * wr[ky * 5 + 4];
                a1 += x1 * wr[ky * 5 + 0] + x2 * wr[ky * 5 + 1] + x3 * wr[ky * 5 + 2]
                    + x4 * wr[ky * 5 + 3] + x5 * wr[ky * 5 + 4];
            }
            outp[pos] = a0;
            outp[pos + 1] = a1;
            ls += a0 + a1;
            lq += a0 * a0 + a1 * a1;
        }
        for (int o = 16; o; o >>= 1) {
            ls += __shfl_xor_sync(0xffffffffu, ls, o);
            lq += __shfl_xor_sync(0xffffffffu, lq, o);
        }
        if (lane == 0) { s_rs[wid] = ls; s_rq[wid] = lq; }
        __syncthreads();
        if (tid == 0) {
            float a = 0.f, b2 = 0.f;
#pragma unroll
            for (int i = 0; i < 8; i++) { a += s_rs[i]; b2 += s_rq[i]; }
            s_sum[ocn] = a; s_sq[ocn] = b2;
        }
        __syncthreads();
    }
    if (tid < 32) {
        g_ps1[n * 32 + tid] = s_sum[tid];
        g_pq1[n * 32 + tid] = s_sq[tid];
    }
}

// ---------------- BN stats: deterministic tree reduce over per-image partials ----------------
__global__ void __launch_bounds__(256) k_bnstats(int which,
                                                 const float* __restrict__ gamma,
                                                 const float* __restrict__ beta) {
    const int C = (which == 1) ? 32 : 64;
    const float* ps = (which == 1) ? g_ps1 : g_ps2;
    const float* pq = (which == 1) ? g_pq1 : g_pq2;
    float* scale = (which == 1) ? g_bns1 : g_bns2;
    float* shift = (which == 1) ? g_bnb1 : g_bnb2;
    const float inv_count = (which == 1) ? (1.f / (4096.f * 576.f)) : (1.f / (4096.f * 64.f));

    int c = blockIdx.x, tid = threadIdx.x;
    __shared__ float sA[8], sB[8];
    float s = 0.f, q = 0.f;
    for (int i = tid; i < NB; i += 256) { s += ps[i * C + c]; q += pq[i * C + c]; }
    for (int o = 16; o; o >>= 1) {
        s += __shfl_xor_sync(0xffffffffu, s, o);
        q += __shfl_xor_sync(0xffffffffu, q, o);
    }
    if ((tid & 31) == 0) { sA[tid >> 5] = s; sB[tid >> 5] = q; }
    __syncthreads();
    if (tid == 0) {
        float ts = 0.f, tq = 0.f;
        for (int i = 0; i < 8; i++) { ts += sA[i]; tq += sB[i]; }
        float mean = ts * inv_count;
        float var = tq * inv_count - mean * mean;
        float sc = gamma[c] * rsqrtf(var + 1e-5f);
        scale[c] = sc;
        shift[c] = beta[c] - mean * sc;
    }
}

// ---------------- BN + maxpool2x2 + relu ----------------
template <int STAGE>
__global__ void __launch_bounds__(256) k_bnpool() {
    constexpr int C = (STAGE == 1) ? 32 : 64;
    constexpr int HI = (STAGE == 1) ? 24 : 8;
    constexpr int HO = HI / 2;
    const float* in = (STAGE == 1) ? g_conv1 : g_conv2;
    float* out = (STAGE == 1) ? g_pool1 : g_pool2;
    const float* scale = (STAGE == 1) ? g_bns1 : g_bns2;
    const float* shift = (STAGE == 1) ? g_bnb1 : g_bnb2;

    int idx = blockIdx.x * 256 + threadIdx.x;
    constexpr int total = NB * C * HO * HO;
    if (idx >= total) return;
    int x = idx % HO;
    int t = idx / HO;
    int y = t % HO; t /= HO;
    int c = t % C;
    int n = t / C;
    const float* ip = in + (((size_t)n * C + c) * HI + 2 * y) * HI + 2 * x;
    float sc = scale[c], sh = shift[c];
    float v0 = ip[0] * sc + sh;
    float v1 = ip[1] * sc + sh;
    float v2 = ip[HI] * sc + sh;
    float v3 = ip[HI + 1] * sc + sh;
    float m = fmaxf(fmaxf(v0, v1), fmaxf(v2, v3));
    out[idx] = fmaxf(m, 0.f);
}

// ---------------- conv2: implicit-im2col GEMM, 1 image/block ----------------
// M = 64 positions, N = 64 out-channels, K = 800. Thread tile 4 pos x 4 oc.
__global__ void __launch_bounds__(256) k_conv2(const float* __restrict__ bias) {
    __shared__ __align__(16) float s_in[32 * 144];     // 18 KB
    __shared__ __align__(16) float s_w[100 * 64];      // 25.6 KB, [k][oc]
    __shared__ int s_kb[100];
    __shared__ float s_sum[64], s_sq[64];
    __shared__ float s_b[64];

    int n = blockIdx.x, tid = threadIdx.x;
    for (int i = tid; i < 4608; i += 256) s_in[i] = g_pool1[(size_t)n * 4608 + i];
    if (tid < 64) s_b[tid] = bias[tid];

    int tp = tid & 15, tc = tid >> 4;
    int oc0 = tc * 4;
    int pos0 = tp * 4;
    int rowoff = (pos0 >> 3) * 12 + (pos0 & 7);   // oy*12 + ox0 (4 consecutive ox share oy)

    float acc[4][4];
#pragma unroll
    for (int i = 0; i < 4; i++)
#pragma unroll
        for (int j = 0; j < 4; j++) acc[i][j] = 0.f;

    for (int kc = 0; kc < 800; kc += 100) {
        __syncthreads();
        for (int i = tid; i < 6400; i += 256) s_w[i] = g_tw2t[kc * 64 + i];
        if (tid < 100) {
            int k = kc + tid;
            int ic = k / 25;
            int r = k - ic * 25;
            int ky = r / 5;
            int kx = r - ky * 5;
            s_kb[tid] = ic * 144 + ky * 12 + kx;
        }
        __syncthreads();
#pragma unroll 2
        for (int j = 0; j < 100; j++) {
            int kb = s_kb[j];
            float4 w4 = *reinterpret_cast<const float4*>(&s_w[j * 64 + oc0]);
            const float* xp = &s_in[kb + rowoff];
            float a0 = xp[0], a1 = xp[1], a2 = xp[2], a3 = xp[3];
            acc[0][0] += a0 * w4.x; acc[0][1] += a0 * w4.y; acc[0][2] += a0 * w4.z; acc[0][3] += a0 * w4.w;
            acc[1][0] += a1 * w4.x; acc[1][1] += a1 * w4.y; acc[1][2] += a1 * w4.z; acc[1][3] += a1 * w4.w;
            acc[2][0] += a2 * w4.x; acc[2][1] += a2 * w4.y; acc[2][2] += a2 * w4.z; acc[2][3] += a2 * w4.w;
            acc[3][0] += a3 * w4.x; acc[3][1] += a3 * w4.y; acc[3][2] += a3 * w4.z; acc[3][3] += a3 * w4.w;
        }
    }

    // bias + store + BN partials
    float ls[4] = {0.f, 0.f, 0.f, 0.f}, lq[4] = {0.f, 0.f, 0.f, 0.f};
#pragma unroll
    for (int ii = 0; ii < 4; ii++) {
        int pos = pos0 + ii;
#pragma unroll
        for (int jj = 0; jj < 4; jj++) {
            float v = acc[ii][jj] + s_b[oc0 + jj];
            g_conv2[((size_t)n * 64 + oc0 + jj) * 64 + pos] = v;
            ls[jj] += v;
            lq[jj] += v * v;
        }
    }
    // channel oc0+jj is owned by the 16 lanes sharing tc (lanes are a warp half)
#pragma unroll
    for (int jj = 0; jj < 4; jj++) {
        for (int o = 8; o; o >>= 1) {
            ls[jj] += __shfl_xor_sync(0xffffffffu, ls[jj], o);
            lq[jj] += __shfl_xor_sync(0xffffffffu, lq[jj], o);
        }
    }
    if (tp == 0) {
#pragma unroll
        for (int jj = 0; jj < 4; jj++) { s_sum[oc0 + jj] = ls[jj]; s_sq[oc0 + jj] = lq[jj]; }
    }
    __syncthreads();
    if (tid < 64) {
        g_ps2[n * 64 + tid] = s_sum[tid];
        g_pq2[n * 64 + tid] = s_sq[tid];
    }
}

// ---------------- fc1: [4096,1024] @ [512,1024]^T + b, relu ----------------
// BM=64, BN=64, BK=16, 256 threads, 4x4 thread tiles.
__global__ void __launch_bounds__(256) k_fc1(const float* __restrict__ bias) {
    __shared__ __align__(16) float As[16][68];
    __shared__ __align__(16) float Bs[16][68];
    int tid = threadIdx.x;
    int brow = blockIdx.y * 64, bcol = blockIdx.x * 64;
    int ty = tid >> 4, tx = tid & 15;
    int lr = tid >> 2;            // 0..63
    int lk = (tid & 3) * 4;       // 0,4,8,12
    float acc[4][4];
#pragma unroll
    for (int i = 0; i < 4; i++)
#pragma unroll
        for (int j = 0; j < 4; j++) acc[i][j] = 0.f;

    const float* Ab = g_pool2 + (size_t)(brow + lr) * 1024 + lk;
    const float* Bb = g_twf1 + (size_t)(bcol + lr) * 1024 + lk;

    for (int kb = 0; kb < 1024; kb += 16) {
        float4 av = *reinterpret_cast<const float4*>(Ab + kb);
        float4 bv = *reinterpret_cast<const float4*>(Bb + kb);
        __syncthreads();
        As[lk + 0][lr] = av.x; As[lk + 1][lr] = av.y; As[lk + 2][lr] = av.z; As[lk + 3][lr] = av.w;
        Bs[lk + 0][lr] = bv.x; Bs[lk + 1][lr] = bv.y; Bs[lk + 2][lr] = bv.z; Bs[lk + 3][lr] = bv.w;
        __syncthreads();
#pragma unroll
        for (int k = 0; k < 16; k++) {
            float4 a4 = *reinterpret_cast<const float4*>(&As[k][ty * 4]);
            float4 b4 = *reinterpret_cast<const float4*>(&Bs[k][tx * 4]);
            acc[0][0] += a4.x * b4.x; acc[0][1] += a4.x * b4.y; acc[0][2] += a4.x * b4.z; acc[0][3] += a4.x * b4.w;
            acc[1][0] += a4.y * b4.x; acc[1][1] += a4.y * b4.y; acc[1][2] += a4.y * b4.z; acc[1][3] += a4.y * b4.w;
            acc[2][0] += a4.z * b4.x; acc[2][1] += a4.z * b4.y; acc[2][2] += a4.z * b4.z; acc[2][3] += a4.z * b4.w;
            acc[3][0] += a4.w * b4.x; acc[3][1] += a4.w * b4.y; acc[3][2] += a4.w * b4.z; acc[3][3] += a4.w * b4.w;
        }
    }
#pragma unroll
    for (int i = 0; i < 4; i++) {
        int row = brow + ty * 4 + i;
#pragma unroll
        for (int j = 0; j < 4; j++) {
            int col = bcol + tx * 4 + j;
            g_fc1o[(size_t)row * 512 + col] = fmaxf(acc[i][j] + __ldg(&bias[col]), 0.f);
        }
    }
}

// ---------------- fc2: [4096,512] @ [10,512]^T + b -> out ----------------
__global__ void __launch_bounds__(256) k_fc2(const float* __restrict__ bias,
                                             float* __restrict__ out) {
    __shared__ float s_w[5120];
    __shared__ float s_b[10];
    int tid = threadIdx.x;
    for (int i = tid; i < 5120; i += 256) s_w[i] = g_twf2[i];
    if (tid < 10) s_b[tid] = bias[tid];
    __syncthreads();
    int wid = tid >> 5, lane = tid & 31;
    int img = blockIdx.x * 8 + wid;
    const float* xr = g_fc1o + (size_t)img * 512;
    float acc[10];
#pragma unroll
    for (int j = 0; j < 10; j++) acc[j] = 0.f;
    for (int k = lane; k < 512; k += 32) {
        float xv = xr[k];
#pragma unroll
        for (int j = 0; j < 10; j++) acc[j] += xv * s_w[j * 512 + k];
    }
#pragma unroll
    for (int j = 0; j < 10; j++)
        for (int o = 16; o; o >>= 1) acc[j] += __shfl_xor_sync(0xffffffffu, acc[j], o);
    if (lane == 0) {
#pragma unroll
        for (int j = 0; j < 10; j++) out[(size_t)img * 10 + j] = acc[j] + s_b[j];
    }
}

// ---------------- launch ----------------
extern "C" void kernel_launch(void* const* d_in, const int* in_sizes, int n_in,
                              void* d_out, int out_size) {
    const float* x   = (const float*)d_in[0];
    const float* w1  = (const float*)d_in[1];
    const float* b1  = (const float*)d_in[2];
    const float* ga1 = (const float*)d_in[3];
    const float* be1 = (const float*)d_in[4];
    const float* w2  = (const float*)d_in[5];
    const float* b2  = (const float*)d_in[6];
    const float* ga2 = (const float*)d_in[7];
    const float* be2 = (const float*)d_in[8];
    const float* wf1 = (const float*)d_in[9];
    const float* bf1 = (const float*)d_in[10];
    const float* wf2 = (const float*)d_in[11];
    const float* bf2 = (const float*)d_in[12];
    float* out = (float*)d_out;

    k_ternarize<<<32, 256>>>(w1, 0, 25);
    k_ternarize<<<64, 256>>>(w2, 1, 800);
    k_ternarize<<<512, 256>>>(wf1, 2, 1024);
    k_ternarize<<<10, 256>>>(wf2, 3, 512);
    k_transpose_w2<<<200, 256>>>();

    k_conv1<<<NB, 256>>>(x, b1);
    k_bnstats<<<32, 256>>>(1, ga1, be1);
    k_bnpool<1><<<(NB * 32 * 144 + 255) / 256, 256>>>();

    k_conv2<<<NB, 256>>>(b2);
    k_bnstats<<<64, 256>>>(2, ga2, be2);
    k_bnpool<2><<<(NB * 64 * 16 + 255) / 256, 256>>>();

    k_fc1<<<dim3(512 / 64, NB / 64), 256>>>(bf1);
    k_fc2<<<NB / 8, 256>>>(bf2, out);
}